// round 17
// baseline (speedup 1.0000x reference)
#include <cuda_runtime.h>
#include <cuda_bf16.h>

#define NN 50000
#define EE 800000
#define DD 128

typedef unsigned int u32;

// ---------------- scratch (device globals: no allocation allowed) ----------
__device__ float g_bufA[(size_t)NN * DD];   // GEMM output g (per layer)
__device__ float g_bufB[(size_t)NN * DD];   // layer-1 accumulator
__device__ float g_dis[NN];
__device__ int   g_deg[NN];
__device__ int2  g_edge[EE];                // (src, dst)
__device__ int   g_is64;
// W fragments in mma B-layout (m16n8k16, col), bf16 hi/lo interleaved:
// index [(kstep*16 + ntile)*32 + lane] -> uint4 {bh0, bh1, bl0, bl1}
__device__ uint4 g_wf[2][4096];

// ---------------- mma helpers ------------------------------------------------
__device__ __forceinline__ void mma_bf16(float* c, const u32* a, u32 b0, u32 b1) {
    asm volatile(
        "mma.sync.aligned.m16n8k16.row.col.f32.bf16.bf16.f32 "
        "{%0,%1,%2,%3}, {%4,%5,%6,%7}, {%8,%9}, {%0,%1,%2,%3};"
        : "+f"(c[0]), "+f"(c[1]), "+f"(c[2]), "+f"(c[3])
        : "r"(a[0]), "r"(a[1]), "r"(a[2]), "r"(a[3]), "r"(b0), "r"(b1));
}
__device__ __forceinline__ void ldm4(u32* a, u32 saddr) {
    asm volatile("ldmatrix.sync.aligned.m8n8.x4.shared.b16 {%0,%1,%2,%3}, [%4];"
                 : "=r"(a[0]), "=r"(a[1]), "=r"(a[2]), "=r"(a[3]) : "r"(saddr));
}

// ---------------- (1) dtype detect + deg init -------------------------------
// edge_index declared int64, but JAX w/o x64 silently emits int32. For int64
// LE values < 50000, every odd 32-bit word is 0.
__global__ void detect_init_kernel(const int* __restrict__ ei32, int n) {
    int i = blockIdx.x * blockDim.x + threadIdx.x;
    if (i < n) g_deg[i] = 1;  // self-loop
    if (i == 0) {
        int is64 = 1;
        for (int k = 0; k < 64; k++)
            if (ei32[2 * k + 1] != 0) { is64 = 0; break; }
        g_is64 = is64;
    }
}

// ---------------- (2) decode edges + dst degree ------------------------------
__global__ void prep_edges_kernel(const void* __restrict__ ei_raw, int E, int n) {
    int e = blockIdx.x * blockDim.x + threadIdx.x;
    if (e >= E) return;
    int s, d;
    if (g_is64) {
        const long long* ei = (const long long*)ei_raw;
        s = (int)ei[e];
        d = (int)ei[(size_t)E + e];
    } else {
        const int* ei = (const int*)ei_raw;
        s = ei[e];
        d = ei[(size_t)E + e];
    }
    if (s < 0) s = 0; if (s >= n) s = n - 1;
    if (d < 0) d = 0; if (d >= n) d = n - 1;
    g_edge[e] = make_int2(s, d);
    atomicAdd(&g_deg[d], 1);
}

// ---------------- (3) dis = rsqrt(deg)  +  W fragment precompute -------------
// t < 8192: build interleaved bf16 hi/lo B-fragments for both layers.
__global__ void prep2_kernel(const float* __restrict__ W1,
                             const float* __restrict__ W2, int n) {
    int t = blockIdx.x * blockDim.x + threadIdx.x;
    if (t < n) g_dis[t] = rsqrtf((float)g_deg[t]);
    if (t < 8192) {
        int layer = t >> 12;          // 0/1
        int q     = t & 4095;
        int lane  = q & 31;
        int nt    = (q >> 5) & 15;
        int ks    = (q >> 9) & 7;
        const float* W = layer ? W2 : W1;
        int k0 = ks * 16 + (lane & 3) * 2;
        int nn = nt * 8 + (lane >> 2);
        float w00 = W[(k0 + 0) * DD + nn];
        float w01 = W[(k0 + 1) * DD + nn];
        float w10 = W[(k0 + 8) * DD + nn];
        float w11 = W[(k0 + 9) * DD + nn];
        __nv_bfloat16 h00 = __float2bfloat16_rn(w00);
        __nv_bfloat16 h01 = __float2bfloat16_rn(w01);
        __nv_bfloat16 h10 = __float2bfloat16_rn(w10);
        __nv_bfloat16 h11 = __float2bfloat16_rn(w11);
        __nv_bfloat162 hp0; hp0.x = h00; hp0.y = h01;
        __nv_bfloat162 hp1; hp1.x = h10; hp1.y = h11;
        __nv_bfloat162 lp0 = __floats2bfloat162_rn(w00 - __bfloat162float(h00),
                                                   w01 - __bfloat162float(h01));
        __nv_bfloat162 lp1 = __floats2bfloat162_rn(w10 - __bfloat162float(h10),
                                                   w11 - __bfloat162float(h11));
        uint4 v;
        v.x = *(u32*)&hp0; v.y = *(u32*)&hp1;
        v.z = *(u32*)&lp0; v.w = *(u32*)&lp1;
        g_wf[layer][q] = v;
    }
}

// ---------------- (4) tensor-core GEMM ---------------------------------------
// g[r][c] = dis[r] * sum_k pre(X[r][k]) * W[k][c]
// pre(x)  = PRE ? relu(dis[r]*x + preb[k]) : x
// 3-product bf16 split: X=Xh+Xl, W=Wh+Wl; D += Ah*Bh + Ah*Bl + Al*Bh.
// Block: 128 thr (4 warps), 64-row tile. Warp w: ALL 64 rows (4 m-tiles),
// cols w*32..+32 (4 n-tiles). MMAs issued as 3 passes over all 16
// accumulators so same-acc RAW ops are 16 issues apart.
#define XS_STRIDE 136   // 128 + 8 bf16 pad -> conflict-free ldmatrix

template <bool PRE>
__global__ void __launch_bounds__(128) gemm_kernel(
    const float* __restrict__ X, const uint4* __restrict__ wf,
    const float* __restrict__ preb,
    float* __restrict__ gout, float* __restrict__ acc, int n)
{
    __shared__ __nv_bfloat16 XsH[64 * XS_STRIDE];
    __shared__ __nv_bfloat16 XsL[64 * XS_STRIDE];

    const int tid  = threadIdx.x;
    const int row0 = blockIdx.x * 64;

    // load X tile, apply PRE, split into bf16 hi/lo
    const float4* X4 = (const float4*)X;
    #pragma unroll
    for (int i = tid; i < 64 * 32; i += 128) {
        int r  = i >> 5;
        int c4 = i & 31;
        int gr = row0 + r;
        float4 v = make_float4(0.f, 0.f, 0.f, 0.f);
        if (gr < n) {
            v = X4[(size_t)gr * 32 + c4];
            if (PRE) {
                float dr = g_dis[gr];
                float4 bb = ((const float4*)preb)[c4];
                v.x = fmaxf(fmaf(dr, v.x, bb.x), 0.f);
                v.y = fmaxf(fmaf(dr, v.y, bb.y), 0.f);
                v.z = fmaxf(fmaf(dr, v.z, bb.z), 0.f);
                v.w = fmaxf(fmaf(dr, v.w, bb.w), 0.f);
            }
        }
        __nv_bfloat16 hx = __float2bfloat16_rn(v.x);
        __nv_bfloat16 hy = __float2bfloat16_rn(v.y);
        __nv_bfloat16 hz = __float2bfloat16_rn(v.z);
        __nv_bfloat16 hw = __float2bfloat16_rn(v.w);
        __nv_bfloat162 h01; h01.x = hx; h01.y = hy;
        __nv_bfloat162 h23; h23.x = hz; h23.y = hw;
        __nv_bfloat162 l01 = __floats2bfloat162_rn(v.x - __bfloat162float(hx),
                                                   v.y - __bfloat162float(hy));
        __nv_bfloat162 l23 = __floats2bfloat162_rn(v.z - __bfloat162float(hz),
                                                   v.w - __bfloat162float(hw));
        int base = r * XS_STRIDE + c4 * 4;
        *(__nv_bfloat162*)&XsH[base]     = h01;
        *(__nv_bfloat162*)&XsH[base + 2] = h23;
        *(__nv_bfloat162*)&XsL[base]     = l01;
        *(__nv_bfloat162*)&XsL[base + 2] = l23;
    }
    __syncthreads();

    const int warp = tid >> 5;     // n-quarter: cols warp*32..+32
    const int lane = tid & 31;

    float accf[4][4][4];
    #pragma unroll
    for (int t = 0; t < 4; t++)
        #pragma unroll
        for (int nt = 0; nt < 4; nt++)
            { accf[t][nt][0]=0.f; accf[t][nt][1]=0.f; accf[t][nt][2]=0.f; accf[t][nt][3]=0.f; }

    u32 baseH = (u32)__cvta_generic_to_shared(XsH);
    u32 baseL = (u32)__cvta_generic_to_shared(XsL);

    // ldmatrix row addresses: lanes 0-7 (m,k), 8-15 (m+8,k), 16-23 (m,k+8), 24-31 (m+8,k+8)
    const int rl    = lane & 7;
    const int sel   = lane >> 3;
    const int rbase = rl + ((sel & 1) ? 8 : 0);
    const int koff8 = (sel & 2) ? 8 : 0;

    const uint4* __restrict__ pw = wf + (warp * 4) * 32 + lane;

    // prefetch B fragments for ks=0
    uint4 b0 = __ldg(&pw[0*32]);
    uint4 b1 = __ldg(&pw[1*32]);
    uint4 b2 = __ldg(&pw[2*32]);
    uint4 b3 = __ldg(&pw[3*32]);

    #pragma unroll
    for (int ks = 0; ks < 8; ks++) {
        int kc = ks * 16 + koff8;

        // prefetch next k-step's B while the MMAs run
        uint4 n0, n1, n2, n3;
        if (ks < 7) {
            const uint4* pn = pw + (ks + 1) * 16 * 32;
            n0 = __ldg(&pn[0*32]);
            n1 = __ldg(&pn[1*32]);
            n2 = __ldg(&pn[2*32]);
            n3 = __ldg(&pn[3*32]);
        }

        // all A fragments for this k-step up front
        u32 aH[4][4], aL[4][4];
        #pragma unroll
        for (int t = 0; t < 4; t++) {
            ldm4(aH[t], baseH + (u32)((rbase + t * 16) * XS_STRIDE + kc) * 2);
            ldm4(aL[t], baseL + (u32)((rbase + t * 16) * XS_STRIDE + kc) * 2);
        }

        // pass 1: Ah * Bh  (16 independent accumulators)
        #pragma unroll
        for (int t = 0; t < 4; t++) {
            mma_bf16(accf[t][0], aH[t], b0.x, b0.y);
            mma_bf16(accf[t][1], aH[t], b1.x, b1.y);
            mma_bf16(accf[t][2], aH[t], b2.x, b2.y);
            mma_bf16(accf[t][3], aH[t], b3.x, b3.y);
        }
        // pass 2: Ah * Bl
        #pragma unroll
        for (int t = 0; t < 4; t++) {
            mma_bf16(accf[t][0], aH[t], b0.z, b0.w);
            mma_bf16(accf[t][1], aH[t], b1.z, b1.w);
            mma_bf16(accf[t][2], aH[t], b2.z, b2.w);
            mma_bf16(accf[t][3], aH[t], b3.z, b3.w);
        }
        // pass 3: Al * Bh
        #pragma unroll
        for (int t = 0; t < 4; t++) {
            mma_bf16(accf[t][0], aL[t], b0.x, b0.y);
            mma_bf16(accf[t][1], aL[t], b1.x, b1.y);
            mma_bf16(accf[t][2], aL[t], b2.x, b2.y);
            mma_bf16(accf[t][3], aL[t], b3.x, b3.y);
        }
        b0 = n0; b1 = n1; b2 = n2; b3 = n3;
    }

    // epilogue: *dis[row], dual store (gout + self-loop-initialized acc)
    #pragma unroll
    for (int t = 0; t < 4; t++) {
        const int gr0 = row0 + t * 16 + (lane >> 2);
        const int gr1 = gr0 + 8;
        float ds0 = (gr0 < n) ? g_dis[gr0] : 0.f;
        float ds1 = (gr1 < n) ? g_dis[gr1] : 0.f;
        #pragma unroll
        for (int nt = 0; nt < 4; nt++) {
            int c  = warp * 32 + nt * 8 + (lane & 3) * 2;
            int ci = c >> 1;
            if (gr0 < n) {
                float2 v = make_float2(accf[t][nt][0] * ds0, accf[t][nt][1] * ds0);
                ((float2*)gout)[(size_t)gr0 * 64 + ci] = v;
                ((float2*)acc )[(size_t)gr0 * 64 + ci] = v;
            }
            if (gr1 < n) {
                float2 v = make_float2(accf[t][nt][2] * ds1, accf[t][nt][3] * ds1);
                ((float2*)gout)[(size_t)gr1 * 64 + ci] = v;
                ((float2*)acc )[(size_t)gr1 * 64 + ci] = v;
            }
        }
    }
}

// ---------------- scatter: acc[dst] += g[src], warp per edge -----------------
__global__ void __launch_bounds__(256) scatter_kernel(
    const float* __restrict__ g, float* __restrict__ acc, int E)
{
    int warp = (blockIdx.x * blockDim.x + threadIdx.x) >> 5;
    int lane = threadIdx.x & 31;
    if (warp >= E) return;
    int2 e = g_edge[warp];

    float4 v = ((const float4*)(g + (size_t)e.x * DD))[lane];
    float* p = acc + (size_t)e.y * DD + lane * 4;
    asm volatile("red.global.add.v4.f32 [%0], {%1, %2, %3, %4};"
                 :: "l"(p), "f"(v.x), "f"(v.y), "f"(v.z), "f"(v.w)
                 : "memory");
}

// ---------------- finalize: out = relu(dis[r]*out + b2[c]), float4 ----------
__global__ void finalize_kernel(float* __restrict__ out,
                                const float* __restrict__ b, int n)
{
    int i = blockIdx.x * blockDim.x + threadIdx.x;
    int total = n * 32;
    if (i >= total) return;
    int r  = i >> 5;
    int c4 = i & 31;
    float ds = g_dis[r];
    float4 v  = ((const float4*)out)[i];
    float4 bb = ((const float4*)b)[c4];
    v.x = fmaxf(fmaf(ds, v.x, bb.x), 0.f);
    v.y = fmaxf(fmaf(ds, v.y, bb.y), 0.f);
    v.z = fmaxf(fmaf(ds, v.z, bb.z), 0.f);
    v.w = fmaxf(fmaf(ds, v.w, bb.w), 0.f);
    ((float4*)out)[i] = v;
}

// ---------------- launch -----------------------------------------------------
extern "C" void kernel_launch(void* const* d_in, const int* in_sizes, int n_in,
                              void* d_out, int out_size)
{
    const float* x   = (const float*)d_in[0];
    const void*  ei  = d_in[1];
    const float* W1  = (const float*)d_in[2];
    const float* b1  = (const float*)d_in[3];
    const float* W2  = (const float*)d_in[4];
    const float* b2  = (const float*)d_in[5];
    float*       out = (float*)d_out;

    const int n = in_sizes[0] / DD;   // 50000
    const int E = in_sizes[1] / 2;    // 800000

    void *pA = nullptr, *pB = nullptr, *pW = nullptr;
    cudaGetSymbolAddress(&pA, g_bufA);
    cudaGetSymbolAddress(&pB, g_bufB);
    cudaGetSymbolAddress(&pW, g_wf);
    float* bufA = (float*)pA;
    float* bufB = (float*)pB;
    const uint4* wf = (const uint4*)pW;

    const int T = 256;
    const int gemm_grid = (n + 63) / 64;
    const int scat_grid = (E * 32 + T - 1) / T;   // warp per edge

    // (1) detect + deg init   (2) decode + degree   (3) dis + W fragments
    detect_init_kernel<<<(n + T - 1) / T, T>>>((const int*)ei, n);
    prep_edges_kernel<<<(E + T - 1) / T, T>>>(ei, E, n);
    prep2_kernel<<<(n + T - 1) / T, T>>>(W1, W2, n);

    // (4) layer-1 GEMM (tensor cores)  <-- profiled slot (launch #4)
    gemm_kernel<false><<<gemm_grid, 128>>>(x, wf, nullptr, bufA, bufB, n);
    // (5) layer-1 scatter
    scatter_kernel<<<scat_grid, T>>>(bufA, bufB, E);

    // (6) layer-2 GEMM (relu(dis*acc1+b1) fused into tile load), acc2=out
    gemm_kernel<true><<<gemm_grid, 128>>>(bufB, wf + 4096, b1, bufA, out, n);
    // (7) layer-2 scatter
    scatter_kernel<<<scat_grid, T>>>(bufA, out, E);

    // (8) out = relu(dis*acc2 + b2)
    finalize_kernel<<<((n * 32) + T - 1) / T, T>>>(out, b2, n);
}